// round 1
// baseline (speedup 1.0000x reference)
#include <cuda_runtime.h>
#include <cstdint>

#define NJ 12
#define DM 128
#define NH 4
#define HD 32
#define TB 16
#define MROWS (TB*NJ)     // 192
#define THREADS 256

#define XS_STRIDE 132
#define QS_STRIDE 36
#define WS_STRIDE 132
#define WOS_STRIDE 36

// shared memory layout (in floats)
#define OFF_XS   0
#define SZ_XS    (MROWS*XS_STRIDE)          // 25344
#define OFF_QH   (OFF_XS + SZ_XS)
#define SZ_QH    (MROWS*QS_STRIDE)          // 6912
#define OFF_KH   (OFF_QH + SZ_QH)
#define OFF_VH   (OFF_KH + SZ_QH)
#define OFF_WB   (OFF_VH + SZ_QH)
#define SZ_WB    (HD*WS_STRIDE)             // 4224
#define OFF_WOS  (OFF_WB + SZ_WB)
#define SZ_WOS   (DM*WOS_STRIDE)            // 4608
#define OFF_BQ   (OFF_WOS + SZ_WOS)
#define OFF_BK   (OFF_BQ + DM)
#define OFF_BV   (OFF_BK + DM)
#define OFF_BO   (OFF_BV + DM)
#define OFF_ADJ  (OFF_BO + DM)              // 12*12
#define OFF_KM   (OFF_ADJ + NJ*NJ)          // 192
#define SM_FLOATS (OFF_KM + MROWS)          // 55760 floats = 223040 B

__device__ __forceinline__ float tf32r(float f) {
    unsigned r;
    asm("cvt.rna.tf32.f32 %0, %1;" : "=r"(r) : "f"(f));
    return __uint_as_float(r);
}

__device__ __forceinline__ void mma_tf32(float* d, const float* a, const float* b) {
    asm volatile(
        "mma.sync.aligned.m16n8k8.row.col.f32.tf32.tf32.f32 "
        "{%0,%1,%2,%3}, {%4,%5,%6,%7}, {%8,%9}, {%0,%1,%2,%3};"
        : "+f"(d[0]), "+f"(d[1]), "+f"(d[2]), "+f"(d[3])
        : "r"(__float_as_uint(a[0])), "r"(__float_as_uint(a[1])),
          "r"(__float_as_uint(a[2])), "r"(__float_as_uint(a[3])),
          "r"(__float_as_uint(b[0])), "r"(__float_as_uint(b[1])));
}

__global__ void __launch_bounds__(THREADS, 1)
cross_joint_attn_kernel(
    const float* __restrict__ x,    // (B, 12, 128)
    const float* __restrict__ vis,  // (B, 12)
    const float* __restrict__ Wq, const float* __restrict__ bq,
    const float* __restrict__ Wk, const float* __restrict__ bk,
    const float* __restrict__ Wv, const float* __restrict__ bv,
    const float* __restrict__ Wo, const float* __restrict__ bo,
    const float* __restrict__ bias_scale,
    const float* __restrict__ adj,  // (12, 12)
    float* __restrict__ out)        // (B, 12, 128)
{
    extern __shared__ float sm[];
    float* Xs   = sm + OFF_XS;
    float* Qh   = sm + OFF_QH;
    float* Kh   = sm + OFF_KH;
    float* Vh   = sm + OFF_VH;
    float* Wbuf = sm + OFF_WB;
    float* Wos  = sm + OFF_WOS;
    float* bqs  = sm + OFF_BQ;
    float* bks  = sm + OFF_BK;
    float* bvs  = sm + OFF_BV;
    float* bos  = sm + OFF_BO;
    float* adjb = sm + OFF_ADJ;
    float* kmsk = sm + OFF_KM;

    const int tid  = threadIdx.x;
    const int lane = tid & 31;
    const int warp = tid >> 5;
    const int cta  = blockIdx.x;
    const int batch0 = cta * TB;

    // ---- stage X (tf32-rounded) ----
    {
        const float4* xg = (const float4*)(x + (size_t)batch0 * NJ * DM);
        #pragma unroll
        for (int i = tid; i < MROWS * DM / 4; i += THREADS) {
            float4 v = xg[i];
            int idx = i * 4;
            int r = idx / DM, c = idx % DM;
            float* dst = Xs + r * XS_STRIDE + c;
            dst[0] = tf32r(v.x); dst[1] = tf32r(v.y);
            dst[2] = tf32r(v.z); dst[3] = tf32r(v.w);
        }
    }
    // ---- stage biases / adjacency / key-mask ----
    if (tid < DM) {
        bqs[tid] = bq[tid]; bks[tid] = bk[tid];
        bvs[tid] = bv[tid]; bos[tid] = bo[tid];
    }
    {
        float bsc = bias_scale[0];
        if (tid < NJ * NJ) adjb[tid] = adj[tid] * bsc;
        if (tid < MROWS)   kmsk[tid] = -10.0f * (1.0f - vis[(size_t)batch0 * NJ + tid]);
    }
    __syncthreads();

    const int mg  = warp >> 1;      // 0..3 : M-group (48 rows each)
    const int ng  = warp & 1;       // 0..1 : N-group
    const int gid = lane >> 2;      // 0..7
    const int tig = lane & 3;       // 0..3

    float y[3][8][4];               // persistent output accumulators
    #pragma unroll
    for (int i = 0; i < 3; i++)
        #pragma unroll
        for (int j = 0; j < 8; j++)
            #pragma unroll
            for (int r = 0; r < 4; r++) y[i][j][r] = 0.0f;

    const float* Wsrc[3] = {Wq, Wk, Wv};
    const float* bsrc[3] = {bqs, bks, bvs};
    float* Cdst[3] = {Qh, Kh, Vh};

    for (int h = 0; h < NH; ++h) {
        // ===== three projection GEMMs: C(192x32) = Xs @ W_h^T + b =====
        for (int t = 0; t < 3; ++t) {
            __syncthreads();  // previous consumers of Wbuf / Cdst done
            {   // stage W rows [h*32, h*32+32), tf32-rounded
                const float4* wg = (const float4*)(Wsrc[t] + (size_t)h * HD * DM);
                #pragma unroll
                for (int i = tid; i < HD * DM / 4; i += THREADS) {
                    float4 v = wg[i];
                    int idx = i * 4;
                    int r = idx / DM, c = idx % DM;
                    float* dst = Wbuf + r * WS_STRIDE + c;
                    dst[0] = tf32r(v.x); dst[1] = tf32r(v.y);
                    dst[2] = tf32r(v.z); dst[3] = tf32r(v.w);
                }
            }
            __syncthreads();

            float acc[3][2][4];
            #pragma unroll
            for (int i = 0; i < 3; i++)
                #pragma unroll
                for (int j = 0; j < 2; j++)
                    #pragma unroll
                    for (int r = 0; r < 4; r++) acc[i][j][r] = 0.0f;

            #pragma unroll
            for (int k0 = 0; k0 < DM; k0 += 8) {
                float a[3][4], b[2][2];
                #pragma unroll
                for (int i = 0; i < 3; i++) {
                    const float* xp = Xs + (mg * 48 + i * 16 + gid) * XS_STRIDE + k0 + tig;
                    a[i][0] = xp[0];
                    a[i][1] = xp[8 * XS_STRIDE];
                    a[i][2] = xp[4];
                    a[i][3] = xp[8 * XS_STRIDE + 4];
                }
                #pragma unroll
                for (int j = 0; j < 2; j++) {
                    const float* wp = Wbuf + (ng * 16 + j * 8 + gid) * WS_STRIDE + k0 + tig;
                    b[j][0] = wp[0];
                    b[j][1] = wp[4];
                }
                #pragma unroll
                for (int i = 0; i < 3; i++)
                    #pragma unroll
                    for (int j = 0; j < 2; j++)
                        mma_tf32(acc[i][j], a[i], b[j]);
            }
            // bias + store (fp32)
            float* C = Cdst[t];
            #pragma unroll
            for (int i = 0; i < 3; i++) {
                int row = mg * 48 + i * 16 + gid;
                #pragma unroll
                for (int j = 0; j < 2; j++) {
                    int col = ng * 16 + j * 8 + 2 * tig;
                    float b0 = bsrc[t][h * HD + col];
                    float b1 = bsrc[t][h * HD + col + 1];
                    C[row * QS_STRIDE + col]       = acc[i][j][0] + b0;
                    C[row * QS_STRIDE + col + 1]   = acc[i][j][1] + b1;
                    C[(row + 8) * QS_STRIDE + col]     = acc[i][j][2] + b0;
                    C[(row + 8) * QS_STRIDE + col + 1] = acc[i][j][3] + b1;
                }
            }
        }
        // ---- stage Wo head slice: Wos[e][d] = Wo[e][h*32+d] (tf32) ----
        #pragma unroll
        for (int i = tid; i < DM * HD / 4; i += THREADS) {
            int idx = i * 4;
            int e = idx / HD, d = idx % HD;
            float4 v = *(const float4*)(Wo + (size_t)e * DM + h * HD + d);
            float* dst = Wos + e * WOS_STRIDE + d;
            dst[0] = tf32r(v.x); dst[1] = tf32r(v.y);
            dst[2] = tf32r(v.z); dst[3] = tf32r(v.w);
        }
        __syncthreads();  // Q/K/V + Wos ready

        // ===== attention (scalar fp32, block-diagonal 12x12 per batch) =====
        {
            int sub = lane >> 4;         // 0..1
            int ln  = lane & 15;         // 0..15
            int lb  = warp * 2 + sub;    // local batch 0..15
            if (ln < NJ) {
                int qrow = lb * NJ + ln;
                float q[HD];
                #pragma unroll
                for (int d = 0; d < HD; d++) q[d] = Qh[qrow * QS_STRIDE + d];

                float s[NJ];
                #pragma unroll
                for (int m = 0; m < NJ; m++) {
                    const float* kp = Kh + (lb * NJ + m) * QS_STRIDE;
                    float dot = 0.0f;
                    #pragma unroll
                    for (int d = 0; d < HD; d++) dot += q[d] * kp[d];
                    s[m] = dot * 0.17677669529663687f + adjb[ln * NJ + m] + kmsk[lb * NJ + m];
                }
                float mx = s[0];
                #pragma unroll
                for (int m = 1; m < NJ; m++) mx = fmaxf(mx, s[m]);
                float sum = 0.0f;
                #pragma unroll
                for (int m = 0; m < NJ; m++) { s[m] = __expf(s[m] - mx); sum += s[m]; }
                float inv = 1.0f / sum;
                #pragma unroll
                for (int m = 0; m < NJ; m++) s[m] *= inv;

                // P@V, overwrite Qh row with tf32-rounded attention output
                #pragma unroll
                for (int d = 0; d < HD; d++) {
                    float acc = 0.0f;
                    #pragma unroll
                    for (int m = 0; m < NJ; m++)
                        acc += s[m] * Vh[(lb * NJ + m) * QS_STRIDE + d];
                    Qh[qrow * QS_STRIDE + d] = tf32r(acc);
                }
            }
        }
        __syncthreads();

        // ===== y += AO(192x32) @ Wo_h^T (accumulate in registers) =====
        #pragma unroll
        for (int k0 = 0; k0 < HD; k0 += 8) {
            float a[3][4], b[8][2];
            #pragma unroll
            for (int i = 0; i < 3; i++) {
                const float* ap = Qh + (mg * 48 + i * 16 + gid) * QS_STRIDE + k0 + tig;
                a[i][0] = ap[0];
                a[i][1] = ap[8 * QS_STRIDE];
                a[i][2] = ap[4];
                a[i][3] = ap[8 * QS_STRIDE + 4];
            }
            #pragma unroll
            for (int j = 0; j < 8; j++) {
                const float* wp = Wos + (ng * 64 + j * 8 + gid) * WOS_STRIDE + k0 + tig;
                b[j][0] = wp[0];
                b[j][1] = wp[4];
            }
            #pragma unroll
            for (int i = 0; i < 3; i++)
                #pragma unroll
                for (int j = 0; j < 8; j++)
                    mma_tf32(y[i][j], a[i], b[j]);
        }
        __syncthreads();  // AO / Wbuf free for next head
    }

    // ===== epilogue: y + bo -> global =====
    #pragma unroll
    for (int i = 0; i < 3; i++) {
        int row = mg * 48 + i * 16 + gid;
        #pragma unroll
        for (int j = 0; j < 8; j++) {
            int col = ng * 64 + j * 8 + 2 * tig;
            float b0 = bos[col];
            float b1 = bos[col + 1];
            size_t base = ((size_t)cta * MROWS + row) * DM + col;
            float2 v0 = make_float2(y[i][j][0] + b0, y[i][j][1] + b1);
            float2 v1 = make_float2(y[i][j][2] + b0, y[i][j][3] + b1);
            *(float2*)(out + base)            = v0;
            *(float2*)(out + base + 8 * DM)   = v1;
        }
    }
}

extern "C" void kernel_launch(void* const* d_in, const int* in_sizes, int n_in,
                              void* d_out, int out_size) {
    const float* x   = (const float*)d_in[0];
    const float* vis = (const float*)d_in[1];
    const float* Wq  = (const float*)d_in[2];
    const float* bq  = (const float*)d_in[3];
    const float* Wk  = (const float*)d_in[4];
    const float* bk  = (const float*)d_in[5];
    const float* Wv  = (const float*)d_in[6];
    const float* bv  = (const float*)d_in[7];
    const float* Wo  = (const float*)d_in[8];
    const float* bo  = (const float*)d_in[9];
    const float* bsc = (const float*)d_in[10];
    const float* adj = (const float*)d_in[11];
    float* out = (float*)d_out;

    const int B = in_sizes[0] / (NJ * DM);   // 16384
    const int grid = B / TB;                 // 1024
    const size_t smem = SM_FLOATS * sizeof(float);

    static bool attr_set = false;
    if (!attr_set) {
        cudaFuncSetAttribute(cross_joint_attn_kernel,
                             cudaFuncAttributeMaxDynamicSharedMemorySize, (int)smem);
        attr_set = true;
    }
    cross_joint_attn_kernel<<<grid, THREADS, smem>>>(
        x, vis, Wq, bq, Wk, bk, Wv, bv, Wo, bo, bsc, adj, out);
}